// round 9
// baseline (speedup 1.0000x reference)
#include <cuda_runtime.h>
#include <math.h>

#define EPS 1e-5f
typedef unsigned long long u64;

// Scratch (device globals — no runtime allocation)
__device__ float g_bufA[(size_t)64*192*56*56];     // 154 MB: conv1 out, region1 in-place
__device__ float g_bufB[(size_t)64*192*28*28];     // 38.5 MB: conv2 out, region2 in-place
__device__ float g_r1wT[(size_t)64*192*9*192];     // 85 MB: r1 weights [g][ci][k][co]
__device__ float g_r2wT[(size_t)16*192*9*192];     // 21 MB: r2 weights [g][ci][k][co]
__device__ float g_c2wT[(size_t)192*192*4];        // conv2 weights [ci][co][k]
__device__ float g_c3wT[(size_t)192*768*4];        // conv3 weights [ci][co][k]

__device__ __forceinline__ float gelu_exact(float x) {
    return 0.5f * x * (1.0f + erff(x * 0.70710678118654752f));
}

// ---- packed fp32x2 helpers (sm_103a FFMA2 path) ----
__device__ __forceinline__ u64 ffma2(u64 a, u64 b, u64 c) {
    u64 d; asm("fma.rn.f32x2 %0, %1, %2, %3;" : "=l"(d) : "l"(a), "l"(b), "l"(c)); return d;
}
__device__ __forceinline__ u64 dup2(float v) {
    u64 d; asm("mov.b64 %0, {%1, %1};" : "=l"(d) : "f"(v)); return d;
}
__device__ __forceinline__ void unpack2(u64 v, float& lo, float& hi) {
    asm("mov.b64 {%0, %1}, %2;" : "=f"(lo), "=f"(hi) : "l"(v));
}

// ---------------------------------------------------------------------------
// Weight transposes
// ---------------------------------------------------------------------------
__global__ void transpose_region_w(const float* __restrict__ w, float* __restrict__ wT, int total)
{
    int idx = blockIdx.x * blockDim.x + threadIdx.x;
    if (idx >= total) return;
    int co = idx % 192;
    int t  = idx / 192;
    int k  = t % 9;  t /= 9;
    int ci = t % 192;
    int g  = t / 192;
    wT[idx] = w[(((size_t)g*192 + co)*192 + ci)*9 + k];
}

__global__ void transpose_conv_w(const float* __restrict__ w, float* __restrict__ wT, int CO, int total)
{
    int idx = blockIdx.x * blockDim.x + threadIdx.x;
    if (idx >= total) return;
    int k  = idx & 3;
    int t  = idx >> 2;
    int co = t % CO;
    int ci = t / CO;
    wT[idx] = w[(((size_t)co*192) + ci)*4 + k];
}

// ---------------------------------------------------------------------------
// conv1
// ---------------------------------------------------------------------------
__global__ __launch_bounds__(192) void conv1_kernel(
    const float* __restrict__ x, const float* __restrict__ w,
    const float* __restrict__ bg, const float* __restrict__ bb,
    const float* __restrict__ bm, const float* __restrict__ bv)
{
    const int oh = blockIdx.x;
    const int b  = blockIdx.y;
    const int co = threadIdx.x;
    __shared__ float s_in[3*4*224];

    for (int i = co; i < 3*4*224; i += 192) {
        int ci = i / (4*224);
        int r  = (i / 224) & 3;
        int c  = i % 224;
        s_in[i] = x[(((size_t)b*3 + ci)*224 + (oh*4 + r))*224 + c];
    }
    float wreg[48];
    #pragma unroll
    for (int k = 0; k < 48; ++k) wreg[k] = w[co*48 + k];
    const float inv  = bg[co] * rsqrtf(bv[co] + EPS);
    const float beta = bb[co] - bm[co]*inv;
    __syncthreads();

    float* outp = &g_bufA[(((size_t)b*192 + co)*56 + oh)*56];
    for (int ow = 0; ow < 56; ++ow) {
        float acc = 0.f;
        #pragma unroll
        for (int ci = 0; ci < 3; ++ci)
            #pragma unroll
            for (int r = 0; r < 4; ++r)
                #pragma unroll
                for (int c = 0; c < 4; ++c)
                    acc = fmaf(wreg[(ci*4+r)*4+c], s_in[(ci*4+r)*224 + ow*4 + c], acc);
        outp[ow] = gelu_exact(acc*inv + beta);
    }
}

// ---------------------------------------------------------------------------
// region conv, packed-f32x2 + row-split. 192 threads: (pair 0..95, grp 0..1).
// grp0 -> output rows 0..3 (28 packed accs), grp1 -> rows 4..6 (21 accs).
// Weight LDG.64 prefetched one ci ahead (double-buffered registers).
// ---------------------------------------------------------------------------
template<int R0, int R1>
__device__ __forceinline__ void region_ci_compute(
    const u64* __restrict__ s_ci,    // &s[ci*56]
    const u64 w2[9], u64* acc)
{
    constexpr int IH0 = (R0 - 1 < 0) ? 0 : (R0 - 1);
    constexpr int IH1 = (R1 + 1 > 7) ? 7 : (R1 + 1);
    #pragma unroll
    for (int ih = IH0; ih < IH1; ++ih) {
        u64 in2[7];
        const u64* rowp = s_ci + ih*8;
        #pragma unroll
        for (int c = 0; c < 7; ++c) in2[c] = rowp[c];        // broadcast LDS.64
        #pragma unroll
        for (int ky = 0; ky < 3; ++ky) {
            const int oh = ih + 1 - ky;
            if (oh < R0 || oh >= R1) continue;               // compile-time pruned
            #pragma unroll
            for (int kx = 0; kx < 3; ++kx) {
                const u64 wk = w2[ky*3 + kx];
                #pragma unroll
                for (int ow = 0; ow < 7; ++ow) {
                    const int iw = ow + kx - 1;
                    if (iw < 0 || iw > 6) continue;
                    acc[(oh - R0)*7 + ow] = ffma2(wk, in2[iw], acc[(oh - R0)*7 + ow]);
                }
            }
        }
    }
}

template<int R0, int R1>
__device__ __forceinline__ void region_mainloop(
    const u64* __restrict__ wp,      // thread's weight base; index (ci*9+k)*96
    const u64* __restrict__ s, u64* acc)
{
    u64 wA[9], wB[9];
    #pragma unroll
    for (int k = 0; k < 9; ++k) wA[k] = wp[k*96];            // ci=0
    for (int ci = 0; ci < 192; ci += 2) {
        const u64* wpn = wp + (size_t)(ci + 1)*9*96;         // prefetch ci+1
        #pragma unroll
        for (int k = 0; k < 9; ++k) wB[k] = wpn[k*96];
        region_ci_compute<R0, R1>(&s[ci*56], wA, acc);
        const int cin = (ci + 2 <= 191) ? (ci + 2) : 191;    // prefetch ci+2 (clamped)
        const u64* wpn2 = wp + (size_t)cin*9*96;
        #pragma unroll
        for (int k = 0; k < 9; ++k) wA[k] = wpn2[k*96];
        region_ci_compute<R0, R1>(&s[(ci + 1)*56], wB, acc);
    }
}

template<int R0, int R1>
__device__ __forceinline__ void region_epilogue(
    const u64* __restrict__ s, u64* acc, float* __restrict__ dst,
    const float* __restrict__ bg, const float* __restrict__ bb,
    const float* __restrict__ bm, const float* __restrict__ bv,
    int g, int pair, int H, int base_h, int base_w)
{
    const int co0 = 2*pair, co1 = 2*pair + 1;
    const int gc0 = g*192 + co0, gc1 = g*192 + co1;
    const float inv0  = bg[gc0] * rsqrtf(bv[gc0] + EPS);
    const float beta0 = bb[gc0] - bm[gc0]*inv0;
    const float inv1  = bg[gc1] * rsqrtf(bv[gc1] + EPS);
    const float beta1 = bb[gc1] - bm[gc1]*inv1;

    #pragma unroll
    for (int j = 0; j < (R1 - R0)*7; ++j) {
        float a0, a1;
        unpack2(acc[j], a0, a1);
        const int row = R0 + j/7, c = j%7;
        float r0, r1, dummy;
        unpack2(s[co0*56 + row*8 + c], r0, dummy);
        unpack2(s[co1*56 + row*8 + c], r1, dummy);
        dst[((size_t)co0*H + base_h + row)*H + base_w + c] = gelu_exact(a0*inv0 + beta0) + r0;
        dst[((size_t)co1*H + base_h + row)*H + base_w + c] = gelu_exact(a1*inv1 + beta1) + r1;
    }
}

__global__ __launch_bounds__(192, 2) void region_kernel(
    const float* __restrict__ wT,
    const float* __restrict__ bg, const float* __restrict__ bb,
    const float* __restrict__ bm, const float* __restrict__ bv,
    int H)   // 56 (grid 8x8) or 28 (grid 4x4)
{
    extern __shared__ u64 s[];          // 192 planes * 56 u64 = 86016 B
    float* buf = (H == 56) ? g_bufA : g_bufB;
    const int GW = H / 7;
    const int b  = blockIdx.x;
    const int g  = blockIdx.y;
    const int t  = threadIdx.x;         // 0..191
    const int pair = (t < 96) ? t : (t - 96);
    const int base_h = (g / GW) * 7;
    const int base_w = (g % GW) * 7;

    const float* src = buf + (size_t)b*192*H*H;
    for (int i = t; i < 192*49; i += 192) {
        int ci = i / 49, p = i % 49;
        float v = src[((size_t)ci*H + base_h + p/7)*H + base_w + p%7];
        s[ci*56 + (p/7)*8 + (p%7)] = dup2(v);
    }
    __syncthreads();

    const u64* wp = reinterpret_cast<const u64*>(wT + (size_t)g*192*9*192) + pair;
    float* dst = buf + (size_t)b*192*H*H;

    if (t < 96) {
        u64 acc[28];
        #pragma unroll
        for (int j = 0; j < 28; ++j) acc[j] = 0ull;
        region_mainloop<0, 4>(wp, s, acc);
        region_epilogue<0, 4>(s, acc, dst, bg, bb, bm, bv, g, pair, H, base_h, base_w);
    } else {
        u64 acc[21];
        #pragma unroll
        for (int j = 0; j < 21; ++j) acc[j] = 0ull;
        region_mainloop<4, 7>(wp, s, acc);
        region_epilogue<4, 7>(s, acc, dst, bg, bb, bm, bv, g, pair, H, base_h, base_w);
    }
}

// ---------------------------------------------------------------------------
// conv2
// ---------------------------------------------------------------------------
__global__ __launch_bounds__(192) void conv2_kernel(
    const float* __restrict__ wT,
    const float* __restrict__ bg, const float* __restrict__ bb,
    const float* __restrict__ bm, const float* __restrict__ bv)
{
    const int q  = blockIdx.x;   // 0..1
    const int oh = blockIdx.y;   // 0..27
    const int b  = blockIdx.z;   // 0..63
    const int co = threadIdx.x;  // 0..191
    __shared__ float s_in[192*2*28];

    for (int i = co; i < 192*2*28; i += 192) {
        int ci = i / 56, r = (i/28) & 1, c = i % 28;
        s_in[i] = g_bufA[(((size_t)b*192 + ci)*56 + 2*oh + r)*56 + q*28 + c];
    }
    __syncthreads();

    float acc[14];
    #pragma unroll
    for (int j = 0; j < 14; ++j) acc[j] = 0.f;

    const float4* w4 = reinterpret_cast<const float4*>(wT) + co;
    for (int ci = 0; ci < 192; ++ci) {
        const float4 wv = w4[ci*192];
        const float4* r0 = reinterpret_cast<const float4*>(&s_in[ci*56]);
        const float4* r1 = reinterpret_cast<const float4*>(&s_in[ci*56 + 28]);
        #pragma unroll
        for (int p = 0; p < 7; ++p) {
            float4 a = r0[p], c = r1[p];
            acc[2*p]   = fmaf(wv.x, a.x, fmaf(wv.y, a.y, fmaf(wv.z, c.x, fmaf(wv.w, c.y, acc[2*p]))));
            acc[2*p+1] = fmaf(wv.x, a.z, fmaf(wv.y, a.w, fmaf(wv.z, c.z, fmaf(wv.w, c.w, acc[2*p+1]))));
        }
    }
    const float inv  = bg[co] * rsqrtf(bv[co] + EPS);
    const float beta = bb[co] - bm[co]*inv;
    float* op = &g_bufB[(((size_t)b*192 + co)*28 + oh)*28 + q*14];
    #pragma unroll
    for (int ow = 0; ow < 14; ++ow) op[ow] = gelu_exact(acc[ow]*inv + beta);
}

// ---------------------------------------------------------------------------
// conv3
// ---------------------------------------------------------------------------
__global__ __launch_bounds__(768) void conv3_kernel(
    const float* __restrict__ wT,
    const float* __restrict__ bg, const float* __restrict__ bb,
    const float* __restrict__ bm, const float* __restrict__ bv,
    float* __restrict__ out)
{
    const int oh = blockIdx.x;   // 0..13
    const int b  = blockIdx.y;   // 0..63
    const int co = threadIdx.x;  // 0..767
    __shared__ float s_in[192*2*28];

    for (int i = co; i < 192*2*28; i += 768) {
        int ci = i / 56, r = (i/28) & 1, c = i % 28;
        s_in[i] = g_bufB[(((size_t)b*192 + ci)*28 + 2*oh + r)*28 + c];
    }
    __syncthreads();

    float acc[14];
    #pragma unroll
    for (int j = 0; j < 14; ++j) acc[j] = 0.f;

    const float4* w4 = reinterpret_cast<const float4*>(wT) + co;
    for (int ci = 0; ci < 192; ++ci) {
        const float4 wv = w4[ci*768];
        const float4* r0 = reinterpret_cast<const float4*>(&s_in[ci*56]);
        const float4* r1 = reinterpret_cast<const float4*>(&s_in[ci*56 + 28]);
        #pragma unroll
        for (int p = 0; p < 7; ++p) {
            float4 a = r0[p], c = r1[p];
            acc[2*p]   = fmaf(wv.x, a.x, fmaf(wv.y, a.y, fmaf(wv.z, c.x, fmaf(wv.w, c.y, acc[2*p]))));
            acc[2*p+1] = fmaf(wv.x, a.z, fmaf(wv.y, a.w, fmaf(wv.z, c.z, fmaf(wv.w, c.w, acc[2*p+1]))));
        }
    }
    const float inv  = bg[co] * rsqrtf(bv[co] + EPS);
    const float beta = bb[co] - bm[co]*inv;
    #pragma unroll
    for (int ow = 0; ow < 14; ++ow)
        out[((size_t)b*196 + oh*14 + ow)*768 + co] = acc[ow]*inv + beta;
}

// ---------------------------------------------------------------------------
extern "C" void kernel_launch(void* const* d_in, const int* in_sizes, int n_in,
                              void* d_out, int out_size)
{
    const float* x       = (const float*)d_in[0];
    const float* c1w     = (const float*)d_in[1];
    const float* b1g = (const float*)d_in[2],  *b1b = (const float*)d_in[3];
    const float* b1m = (const float*)d_in[4],  *b1v = (const float*)d_in[5];
    const float* r1w     = (const float*)d_in[6];
    const float* r1g = (const float*)d_in[7],  *r1b = (const float*)d_in[8];
    const float* r1m = (const float*)d_in[9],  *r1v = (const float*)d_in[10];
    const float* c2w     = (const float*)d_in[11];
    const float* b2g = (const float*)d_in[12], *b2b = (const float*)d_in[13];
    const float* b2m = (const float*)d_in[14], *b2v = (const float*)d_in[15];
    const float* r2w     = (const float*)d_in[16];
    const float* r2g = (const float*)d_in[17], *r2b = (const float*)d_in[18];
    const float* r2m = (const float*)d_in[19], *r2v = (const float*)d_in[20];
    const float* c3w     = (const float*)d_in[21];
    const float* b3g = (const float*)d_in[22], *b3b = (const float*)d_in[23];
    const float* b3m = (const float*)d_in[24], *b3v = (const float*)d_in[25];
    float* out = (float*)d_out;

    float *r1wT, *r2wT, *c2wT, *c3wT;
    cudaGetSymbolAddress((void**)&r1wT, g_r1wT);
    cudaGetSymbolAddress((void**)&r2wT, g_r2wT);
    cudaGetSymbolAddress((void**)&c2wT, g_c2wT);
    cudaGetSymbolAddress((void**)&c3wT, g_c3wT);

    {   // weight transposes
        int t1 = 64*192*192*9;
        transpose_region_w<<<(t1 + 255)/256, 256>>>(r1w, r1wT, t1);
        int t2 = 16*192*192*9;
        transpose_region_w<<<(t2 + 255)/256, 256>>>(r2w, r2wT, t2);
        int t3 = 192*192*4;
        transpose_conv_w<<<(t3 + 255)/256, 256>>>(c2w, c2wT, 192, t3);
        int t4 = 192*768*4;
        transpose_conv_w<<<(t4 + 255)/256, 256>>>(c3w, c3wT, 768, t4);
    }

    const int region_smem = 192*56*sizeof(u64);   // 86016 B
    cudaFuncSetAttribute(region_kernel, cudaFuncAttributeMaxDynamicSharedMemorySize, region_smem);

    conv1_kernel<<<dim3(56, 64), 192>>>(x, c1w, b1g, b1b, b1m, b1v);
    region_kernel<<<dim3(64, 64), 192, region_smem>>>(r1wT, r1g, r1b, r1m, r1v, 56);
    conv2_kernel<<<dim3(2, 28, 64), 192>>>(c2wT, b2g, b2b, b2m, b2v);
    region_kernel<<<dim3(64, 16), 192, region_smem>>>(r2wT, r2g, r2b, r2m, r2v, 28);
    conv3_kernel<<<dim3(14, 64), 768>>>(c3wT, b3g, b3b, b3m, b3v, out);
}

// round 11
// speedup vs baseline: 1.7048x; 1.7048x over previous
#include <cuda_runtime.h>
#include <cuda_bf16.h>
#include <math.h>

#define EPS 1e-5f
typedef unsigned long long u64;

// tcgen05 only exists on the arch-accelerated target; the fatbin also builds a
// plain compute_103 pass where these instructions are illegal. Guard them out
// there — the GB300 always executes the sm_103a cubin.
#if !defined(__CUDA_ARCH__) || defined(__CUDA_ARCH_FEAT_SM103_ALL) || defined(__CUDA_ARCH_FEAT_SM100_ALL) || defined(__CUDA_ARCH_FEAT_SM101_ALL)
#define TC_OK 1
#else
#define TC_OK 0
#endif

// Scratch (device globals — no runtime allocation)
__device__ float g_bufA[(size_t)64*192*56*56];        // conv1 out, region1 in-place
__device__ float g_bufB[(size_t)64*192*28*28];        // conv2 out, region2 in-place
__device__ __nv_bfloat16 g_blob1[(size_t)64*27*24576]; // r1: per (g,kk,cc): [hi 192x64 SW128 | lo]
__device__ __nv_bfloat16 g_blob2[(size_t)16*27*24576]; // r2 likewise
__device__ float g_c2wT[(size_t)192*192*4];           // conv2 weights [ci][co][k]
__device__ float g_c3wT[(size_t)192*768*4];           // conv3 weights [ci][co][k]

__device__ __forceinline__ float gelu_exact(float x) {
    return 0.5f * x * (1.0f + erff(x * 0.70710678118654752f));
}

#if TC_OK
// ---------------- tcgen05 / mbarrier PTX helpers (sm_103a-only) ----------------
__device__ __forceinline__ unsigned smem_u32(const void* p) {
    unsigned a; asm("{ .reg .u64 t; cvta.to.shared.u64 t, %1; cvt.u32.u64 %0, t; }" : "=r"(a) : "l"(p));
    return a;
}
__device__ __forceinline__ bool elect_one() {
    unsigned p;
    asm volatile("{\n\t.reg .pred P;\n\telect.sync _|P, 0xFFFFFFFF;\n\tselp.b32 %0, 1, 0, P;\n\t}" : "=r"(p));
    return p != 0;
}
__device__ __forceinline__ void tc_alloc(unsigned dst_smem, unsigned ncols) {
    asm volatile("tcgen05.alloc.cta_group::1.sync.aligned.shared::cta.b32 [%0], %1;"
                 :: "r"(dst_smem), "r"(ncols) : "memory");
}
__device__ __forceinline__ void tc_dealloc(unsigned tmem, unsigned ncols) {
    asm volatile("tcgen05.dealloc.cta_group::1.sync.aligned.b32 %0, %1;" :: "r"(tmem), "r"(ncols));
}
__device__ __forceinline__ void mbar_init(unsigned mbar, unsigned cnt) {
    asm volatile("mbarrier.init.shared.b64 [%0], %1;" :: "r"(mbar), "r"(cnt) : "memory");
}
__device__ __forceinline__ void mbar_wait(unsigned mbar, unsigned parity) {
    asm volatile(
        "{\n\t.reg .pred P;\n\t"
        "WL%=:\n\t"
        "mbarrier.try_wait.parity.shared.b64 P, [%0], %1, 0x989680;\n\t"
        "@P bra WD%=;\n\t"
        "bra WL%=;\n\t"
        "WD%=:\n\t}"
        :: "r"(mbar), "r"(parity) : "memory");
}
__device__ __forceinline__ void tc_commit(unsigned mbar) {
    asm volatile("tcgen05.commit.cta_group::1.mbarrier::arrive::one.shared::cluster.b64 [%0];"
                 :: "r"(mbar) : "memory");
}
__device__ __forceinline__ void mma_f16(unsigned d, u64 adesc, u64 bdesc, unsigned idesc, unsigned en) {
    asm volatile(
        "{\n\t.reg .pred p;\n\tsetp.ne.u32 p, %4, 0;\n\t"
        "tcgen05.mma.cta_group::1.kind::f16 [%0], %1, %2, %3, {%5, %5, %5, %5}, p;\n\t}"
        :: "r"(d), "l"(adesc), "l"(bdesc), "r"(idesc), "r"(en), "r"(0u) : "memory");
}
__device__ __forceinline__ void ldtm32(unsigned* r, unsigned addr) {
    asm volatile(
        "tcgen05.ld.sync.aligned.32x32b.x32.b32 "
        "{%0, %1, %2, %3, %4, %5, %6, %7, %8, %9, %10, %11, %12, %13, %14, %15, "
        " %16, %17, %18, %19, %20, %21, %22, %23, %24, %25, %26, %27, %28, %29, %30, %31}, [%32];"
        : "=r"(r[0]),  "=r"(r[1]),  "=r"(r[2]),  "=r"(r[3]),
          "=r"(r[4]),  "=r"(r[5]),  "=r"(r[6]),  "=r"(r[7]),
          "=r"(r[8]),  "=r"(r[9]),  "=r"(r[10]), "=r"(r[11]),
          "=r"(r[12]), "=r"(r[13]), "=r"(r[14]), "=r"(r[15]),
          "=r"(r[16]), "=r"(r[17]), "=r"(r[18]), "=r"(r[19]),
          "=r"(r[20]), "=r"(r[21]), "=r"(r[22]), "=r"(r[23]),
          "=r"(r[24]), "=r"(r[25]), "=r"(r[26]), "=r"(r[27]),
          "=r"(r[28]), "=r"(r[29]), "=r"(r[30]), "=r"(r[31])
        : "r"(addr));
}
__device__ __forceinline__ void tc_wait_ld()  { asm volatile("tcgen05.wait::ld.sync.aligned;" ::: "memory"); }
__device__ __forceinline__ u64 make_desc(unsigned addr) {
    return ((u64)2 << 61) | ((u64)1 << 46) | ((u64)64 << 32) | ((u64)1 << 16)
         | (u64)((addr >> 4) & 0x3FFF);
}
#endif // TC_OK

// idesc: F32 accum, BF16 x BF16, M=128, N=192
#define MMA_IDESC 0x8300490u

// ---------------------------------------------------------------------------
// Region weight prep: w[g][co][ci][3][3] fp32 ->
//   blob[(g*9+kk)*3+cc] = [ hi tile 192x64 SW128-swizzled | lo tile ]   (bf16)
// ---------------------------------------------------------------------------
__global__ void prep_region_blob(const float* __restrict__ w, __nv_bfloat16* __restrict__ blob, int total)
{
    int idx = blockIdx.x * blockDim.x + threadIdx.x;
    if (idx >= total) return;
    int j  = idx & 63;
    int t  = idx >> 6;
    int co = t % 192;  t /= 192;
    int cc = t % 3;    t /= 3;
    int kk = t % 9;
    int g  = t / 9;
    int ci = cc*64 + j, ky = kk/3, kx = kk%3;
    float v = w[((((size_t)g*192 + co)*192 + ci)*3 + ky)*3 + kx];
    __nv_bfloat16 h = __float2bfloat16(v);
    __nv_bfloat16 l = __float2bfloat16(v - __bfloat162float(h));
    int off = co*128 + j*2;
    off ^= (off >> 3) & 0x70;                 // SW128 swizzle
    size_t base = ((size_t)((g*9 + kk)*3 + cc)) * 24576;
    blob[base + off/2]         = h;
    blob[base + 12288 + off/2] = l;
}

__global__ void transpose_conv_w(const float* __restrict__ w, float* __restrict__ wT, int CO, int total)
{
    int idx = blockIdx.x * blockDim.x + threadIdx.x;
    if (idx >= total) return;
    int k  = idx & 3;
    int t  = idx >> 2;
    int co = t % CO;
    int ci = t / CO;
    wT[idx] = w[(((size_t)co*192) + ci)*4 + k];
}

// ---------------------------------------------------------------------------
// conv1: x(64,3,224,224) * w(192,3,4,4) stride4 VALID -> bn -> gelu -> bufA
// ---------------------------------------------------------------------------
__global__ __launch_bounds__(192) void conv1_kernel(
    const float* __restrict__ x, const float* __restrict__ w,
    const float* __restrict__ bg, const float* __restrict__ bb,
    const float* __restrict__ bm, const float* __restrict__ bv)
{
    const int oh = blockIdx.x;
    const int b  = blockIdx.y;
    const int co = threadIdx.x;
    __shared__ float s_in[3*4*224];

    for (int i = co; i < 3*4*224; i += 192) {
        int ci = i / (4*224);
        int r  = (i / 224) & 3;
        int c  = i % 224;
        s_in[i] = x[(((size_t)b*3 + ci)*224 + (oh*4 + r))*224 + c];
    }
    float wreg[48];
    #pragma unroll
    for (int k = 0; k < 48; ++k) wreg[k] = w[co*48 + k];
    const float inv  = bg[co] * rsqrtf(bv[co] + EPS);
    const float beta = bb[co] - bm[co]*inv;
    __syncthreads();

    float* outp = &g_bufA[(((size_t)b*192 + co)*56 + oh)*56];
    for (int ow = 0; ow < 56; ++ow) {
        float acc = 0.f;
        #pragma unroll
        for (int ci = 0; ci < 3; ++ci)
            #pragma unroll
            for (int r = 0; r < 4; ++r)
                #pragma unroll
                for (int c = 0; c < 4; ++c)
                    acc = fmaf(wreg[(ci*4+r)*4+c], s_in[(ci*4+r)*224 + ow*4 + c], acc);
        outp[ow] = gelu_exact(acc*inv + beta);
    }
}

// ---------------------------------------------------------------------------
// region_mma: per-tile 3x3 SAME conv as tcgen05 bf16-split GEMM.
// CTA = (b-pair, g). D[128 pos, 192 co] fp32 in TMEM, K = 9 kk x 3 ci-chunks x 64,
// 3 split terms (hi*hi, hi*lo, lo*hi). Epilogue: BN + GELU + residual, in place.
// ---------------------------------------------------------------------------
#define OF_TMEM  0
#define OF_MBAR  8
#define OF_INV   16
#define OF_BETA  (16 + 768)
#define OF_AHI   2048
#define OF_ALO   18432
#define OF_B     34816        /* hi 24576 | lo 24576 */
#define OF_PL    83968        /* 4 planes x (49 rows x 400 B) */
#define PL_STRIDE 19600
#define REGION_SMEM 162368

__global__ __launch_bounds__(256, 1)
void region_mma(const __nv_bfloat16* __restrict__ blob,
                const float* __restrict__ bg, const float* __restrict__ bb,
                const float* __restrict__ bm, const float* __restrict__ bv,
                int H)   // 56 or 28
{
#if TC_OK
    extern __shared__ char smem[];
    float* buf = (H == 56) ? g_bufA : g_bufB;
    const int GW = H / 7;
    const int b0 = blockIdx.x * 2;
    const int g  = blockIdx.y;
    const int base_h = (g / GW) * 7;
    const int base_w = (g % GW) * 7;
    const int t = threadIdx.x, wid = t >> 5, lane = t & 31;
    const unsigned sbase = smem_u32(smem);

    if (wid == 0) tc_alloc(sbase + OF_TMEM, 256);

    // BN coefficient tables
    if (t < 192) {
        int gc = g*192 + t;
        float inv = bg[gc] * rsqrtf(bv[gc] + EPS);
        ((float*)(smem + OF_INV))[t]  = inv;
        ((float*)(smem + OF_BETA))[t] = bb[gc] - bm[gc]*inv;
    }
    if (t == 0) mbar_init(sbase + OF_MBAR, 1);

    // zero the permanent pad rows of A tiles (rows 49-63, 113-127; hi and lo)
    for (int u = t; u < 480; u += 256) {
        int set = u / 240, v = u % 240, rr = v / 8, j = v % 8;
        int m = (rr < 15) ? (49 + rr) : (113 - 15 + rr);
        int off = m*128 + j*16;  off ^= (off >> 3) & 0x70;
        *(float4*)(smem + (set ? OF_ALO : OF_AHI) + off) = make_float4(0.f, 0.f, 0.f, 0.f);
    }

    // bf16 hi/lo planes of the two input tiles: plane[p(49)][ci(192)], 400 B rows
    for (int i = t; i < 2*192*49; i += 256) {
        int ow = i % 7, oh = (i/7) % 7, ci = (i/49) % 192, bl = i / 9408;
        float v = buf[(((size_t)(b0 + bl)*192 + ci)*H + base_h + oh)*H + base_w + ow];
        __nv_bfloat16 h = __float2bfloat16(v);
        __nv_bfloat16 l = __float2bfloat16(v - __bfloat162float(h));
        int p = oh*7 + ow;
        *(__nv_bfloat16*)(smem + OF_PL + (bl*2 + 0)*PL_STRIDE + p*400 + ci*2) = h;
        *(__nv_bfloat16*)(smem + OF_PL + (bl*2 + 1)*PL_STRIDE + p*400 + ci*2) = l;
    }
    __syncthreads();

    unsigned tmem;
    asm volatile("ld.shared.b32 %0, [%1];" : "=r"(tmem) : "r"(sbase + OF_TMEM));

    const float4* bsrc = (const float4*)blob + (size_t)g * 27 * 3072;
    float4 breg[12];
    #pragma unroll
    for (int k = 0; k < 12; ++k) breg[k] = bsrc[t + k*256];   // prefetch iter 0

    const u64 dAhi = make_desc(sbase + OF_AHI);
    const u64 dAlo = make_desc(sbase + OF_ALO);
    const u64 dBhi = make_desc(sbase + OF_B);
    const u64 dBlo = make_desc(sbase + OF_B + 24576);

    #pragma unroll 1
    for (int it = 0; it < 27; ++it) {
        if (it > 0) mbar_wait(sbase + OF_MBAR, (unsigned)((it - 1) & 1));

        // B: straight pre-swizzled copy (hi|lo, 48 KB)
        float4* bdst = (float4*)(smem + OF_B);
        #pragma unroll
        for (int k = 0; k < 12; ++k) bdst[t + k*256] = breg[k];

        // A: gather shifted plane rows into SW128 tiles (hi and lo)
        const int ky = (it/3) / 3, kx = (it/3) % 3, cc = it % 3;
        #pragma unroll
        for (int u = t; u < 2048; u += 256) {
            int set = u >> 10, v = u & 1023, m = v >> 3, j = v & 7;
            int p = m & 63, bl = m >> 6;
            if (p >= 49) continue;                        // permanent zero rows
            float4 val = make_float4(0.f, 0.f, 0.f, 0.f);
            int oh = p/7 + ky - 1, ow = p%7 + kx - 1;
            if (oh >= 0 && oh < 7 && ow >= 0 && ow < 7)
                val = *(const float4*)(smem + OF_PL + (bl*2 + set)*PL_STRIDE
                                       + (oh*7 + ow)*400 + cc*128 + j*16);
            int off = m*128 + j*16;  off ^= (off >> 3) & 0x70;
            *(float4*)(smem + (set ? OF_ALO : OF_AHI) + off) = val;
        }

        // prefetch next iteration's B while MMAs run
        if (it < 26) {
            const float4* nb = bsrc + (size_t)(it + 1) * 3072;
            #pragma unroll
            for (int k = 0; k < 12; ++k) breg[k] = nb[t + k*256];
        }

        asm volatile("fence.proxy.async.shared::cta;" ::: "memory");
        __syncthreads();

        if (wid == 0 && elect_one()) {
            #pragma unroll
            for (int ks = 0; ks < 4; ++ks)
                mma_f16(tmem, dAhi + ks*2, dBhi + ks*2, MMA_IDESC, (it == 0 && ks == 0) ? 0u : 1u);
            #pragma unroll
            for (int ks = 0; ks < 4; ++ks)
                mma_f16(tmem, dAhi + ks*2, dBlo + ks*2, MMA_IDESC, 1u);
            #pragma unroll
            for (int ks = 0; ks < 4; ++ks)
                mma_f16(tmem, dAlo + ks*2, dBhi + ks*2, MMA_IDESC, 1u);
            tc_commit(sbase + OF_MBAR);
        }
    }
    mbar_wait(sbase + OF_MBAR, 0u);                       // iter 26: parity 0
    asm volatile("tcgen05.fence::after_thread_sync;" ::: "memory");

    // Epilogue: warps 0-3 read D rows (lanes = positions), BN+GELU+residual, write back
    if (wid < 4) {
        const int m = wid*32 + lane, p = m & 63, bl = m >> 6;
        const bool live = (p < 49);
        const float* sinv  = (const float*)(smem + OF_INV);
        const float* sbeta = (const float*)(smem + OF_BETA);
        float* dstb = buf + ((size_t)(b0 + bl)*192) * H * H;
        const size_t pix = (size_t)(base_h + p/7)*H + base_w + p%7;
        #pragma unroll 1
        for (int c0 = 0; c0 < 192; c0 += 32) {
            unsigned r[32];
            ldtm32(r, tmem + c0);
            tc_wait_ld();
            if (live) {
                #pragma unroll
                for (int c = 0; c < 32; ++c) {
                    int co = c0 + c;
                    float a = __uint_as_float(r[c]);
                    float y = gelu_exact(a*sinv[co] + sbeta[co]);
                    float rh = __bfloat162float(*(const __nv_bfloat16*)
                        (smem + OF_PL + (bl*2 + 0)*PL_STRIDE + p*400 + co*2));
                    float rl = __bfloat162float(*(const __nv_bfloat16*)
                        (smem + OF_PL + (bl*2 + 1)*PL_STRIDE + p*400 + co*2));
                    dstb[(size_t)co*H*H + pix] = y + rh + rl;
                }
            }
        }
    }
    __syncthreads();
    if (wid == 0) tc_dealloc(tmem, 256);
#endif // TC_OK — fallback pass compiles an empty body; GB300 runs the sm_103a cubin
}

// ---------------------------------------------------------------------------
// conv2: bufA * wT2[ci][co][k] stride2 -> bn -> gelu -> bufB
// ---------------------------------------------------------------------------
__global__ __launch_bounds__(192) void conv2_kernel(
    const float* __restrict__ wT,
    const float* __restrict__ bg, const float* __restrict__ bb,
    const float* __restrict__ bm, const float* __restrict__ bv)
{
    const int q  = blockIdx.x;
    const int oh = blockIdx.y;
    const int b  = blockIdx.z;
    const int co = threadIdx.x;
    __shared__ float s_in[192*2*28];

    for (int i = co; i < 192*2*28; i += 192) {
        int ci = i / 56, r = (i/28) & 1, c = i % 28;
        s_in[i] = g_bufA[(((size_t)b*192 + ci)*56 + 2*oh + r)*56 + q*28 + c];
    }
    __syncthreads();

    float acc[14];
    #pragma unroll
    for (int j = 0; j < 14; ++j) acc[j] = 0.f;

    const float4* w4 = reinterpret_cast<const float4*>(wT) + co;
    for (int ci = 0; ci < 192; ++ci) {
        const float4 wv = w4[ci*192];
        const float4* r0 = reinterpret_cast<const float4*>(&s_in[ci*56]);
        const float4* r1 = reinterpret_cast<const float4*>(&s_in[ci*56 + 28]);
        #pragma unroll
        for (int p = 0; p < 7; ++p) {
            float4 a = r0[p], c = r1[p];
            acc[2*p]   = fmaf(wv.x, a.x, fmaf(wv.y, a.y, fmaf(wv.z, c.x, fmaf(wv.w, c.y, acc[2*p]))));
            acc[2*p+1] = fmaf(wv.x, a.z, fmaf(wv.y, a.w, fmaf(wv.z, c.z, fmaf(wv.w, c.w, acc[2*p+1]))));
        }
    }
    const float inv  = bg[co] * rsqrtf(bv[co] + EPS);
    const float beta = bb[co] - bm[co]*inv;
    float* op = &g_bufB[(((size_t)b*192 + co)*28 + oh)*28 + q*14];
    #pragma unroll
    for (int ow = 0; ow < 14; ++ow) op[ow] = gelu_exact(acc[ow]*inv + beta);
}

// ---------------------------------------------------------------------------
// conv3: bufB * wT3[ci][co][k] stride2 -> bn -> transposed write (B,196,768)
// ---------------------------------------------------------------------------
__global__ __launch_bounds__(768) void conv3_kernel(
    const float* __restrict__ wT,
    const float* __restrict__ bg, const float* __restrict__ bb,
    const float* __restrict__ bm, const float* __restrict__ bv,
    float* __restrict__ out)
{
    const int oh = blockIdx.x;
    const int b  = blockIdx.y;
    const int co = threadIdx.x;
    __shared__ float s_in[192*2*28];

    for (int i = co; i < 192*2*28; i += 768) {
        int ci = i / 56, r = (i/28) & 1, c = i % 28;
        s_in[i] = g_bufB[(((size_t)b*192 + ci)*28 + 2*oh + r)*28 + c];
    }
    __syncthreads();

    float acc[14];
    #pragma unroll
    for (int j = 0; j < 14; ++j) acc[j] = 0.f;

    const float4* w4 = reinterpret_cast<const float4*>(wT) + co;
    for (int ci = 0; ci < 192; ++ci) {
        const float4 wv = w4[ci*768];
        const float4* r0 = reinterpret_cast<const float4*>(&s_in[ci*56]);
        const float4* r1 = reinterpret_cast<const float4*>(&s_in[ci*56 + 28]);
        #pragma unroll
        for (int p = 0; p < 7; ++p) {
            float4 a = r0[p], c = r1[p];
            acc[2*p]   = fmaf(wv.x, a.x, fmaf(wv.y, a.y, fmaf(wv.z, c.x, fmaf(wv.w, c.y, acc[2*p]))));
            acc[2*p+1] = fmaf(wv.x, a.z, fmaf(wv.y, a.w, fmaf(wv.z, c.z, fmaf(wv.w, c.w, acc[2*p+1]))));
        }
    }
    const float inv  = bg[co] * rsqrtf(bv[co] + EPS);
    const float beta = bb[co] - bm[co]*inv;
    #pragma unroll
    for (int ow = 0; ow < 14; ++ow)
        out[((size_t)b*196 + oh*14 + ow)*768 + co] = acc[ow]*inv + beta;
}

// ---------------------------------------------------------------------------
extern "C" void kernel_launch(void* const* d_in, const int* in_sizes, int n_in,
                              void* d_out, int out_size)
{
    const float* x       = (const float*)d_in[0];
    const float* c1w     = (const float*)d_in[1];
    const float* b1g = (const float*)d_in[2],  *b1b = (const float*)d_in[3];
    const float* b1m = (const float*)d_in[4],  *b1v = (const float*)d_in[5];
    const float* r1w     = (const float*)d_in[6];
    const float* r1g = (const float*)d_in[7],  *r1b = (const float*)d_in[8];
    const float* r1m = (const float*)d_in[9],  *r1v = (const float*)d_in[10];
    const float* c2w     = (const float*)d_in[11];
    const float* b2g = (const float*)d_in[12], *b2b = (const float*)d_in[13];
    const float* b2m = (const float*)d_in[14], *b2v = (const float*)d_in[15];
    const float* r2w     = (const float*)d_in[16];
    const float* r2g = (const float*)d_in[17], *r2b = (const float*)d_in[18];
    const float* r2m = (const float*)d_in[19], *r2v = (const float*)d_in[20];
    const float* c3w     = (const float*)d_in[21];
    const float* b3g = (const float*)d_in[22], *b3b = (const float*)d_in[23];
    const float* b3m = (const float*)d_in[24], *b3v = (const float*)d_in[25];
    float* out = (float*)d_out;

    __nv_bfloat16 *blob1, *blob2;
    float *c2wT, *c3wT;
    cudaGetSymbolAddress((void**)&blob1, g_blob1);
    cudaGetSymbolAddress((void**)&blob2, g_blob2);
    cudaGetSymbolAddress((void**)&c2wT, g_c2wT);
    cudaGetSymbolAddress((void**)&c3wT, g_c3wT);

    {   // weight prep
        int t1 = 64*9*3*192*64;
        prep_region_blob<<<(t1 + 255)/256, 256>>>(r1w, blob1, t1);
        int t2 = 16*9*3*192*64;
        prep_region_blob<<<(t2 + 255)/256, 256>>>(r2w, blob2, t2);
        int t3 = 192*192*4;
        transpose_conv_w<<<(t3 + 255)/256, 256>>>(c2w, c2wT, 192, t3);
        int t4 = 192*768*4;
        transpose_conv_w<<<(t4 + 255)/256, 256>>>(c3w, c3wT, 768, t4);
    }

    cudaFuncSetAttribute(region_mma, cudaFuncAttributeMaxDynamicSharedMemorySize, REGION_SMEM);

    conv1_kernel<<<dim3(56, 64), 192>>>(x, c1w, b1g, b1b, b1m, b1v);
    region_mma<<<dim3(32, 64), 256, REGION_SMEM>>>(blob1, r1g, r1b, r1m, r1v, 56);
    conv2_kernel<<<dim3(2, 28, 64), 192>>>(c2wT, b2g, b2b, b2m, b2v);
    region_mma<<<dim3(32, 16), 256, REGION_SMEM>>>(blob2, r2g, r2b, r2m, r2v, 28);
    conv3_kernel<<<dim3(14, 64), 768>>>(c3wT, b3g, b3b, b3m, b3v, out);
}

// round 12
// speedup vs baseline: 1.7169x; 1.0071x over previous
#include <cuda_runtime.h>
#include <cuda_bf16.h>
#include <math.h>

#define EPS 1e-5f
typedef unsigned long long u64;

// tcgen05 only exists on the arch-accelerated target; the fatbin also builds a
// plain compute_103 pass where these instructions are illegal. Guard them out
// there — the GB300 always executes the sm_103a cubin.
#if !defined(__CUDA_ARCH__) || defined(__CUDA_ARCH_FEAT_SM103_ALL) || defined(__CUDA_ARCH_FEAT_SM100_ALL) || defined(__CUDA_ARCH_FEAT_SM101_ALL)
#define TC_OK 1
#else
#define TC_OK 0
#endif

// Scratch (device globals — no runtime allocation)
__device__ float g_bufA[(size_t)64*192*56*56];        // conv1 out, region1 in-place
__device__ float g_bufB[(size_t)64*192*28*28];        // conv2 out, region2 in-place
__device__ __nv_bfloat16 g_blob1[(size_t)64*27*24576]; // r1: per (g,kk,cc): [hi 192x64 SW128 | lo]
__device__ __nv_bfloat16 g_blob2[(size_t)16*27*24576]; // r2 likewise
__device__ float g_c2wT[(size_t)192*192*4];           // conv2 weights [ci][co][k]
__device__ float g_c3wT[(size_t)192*768*4];           // conv3 weights [ci][co][k]

__device__ __forceinline__ float gelu_exact(float x) {
    return 0.5f * x * (1.0f + erff(x * 0.70710678118654752f));
}

#if TC_OK
// ---------------- tcgen05 / TMA / mbarrier PTX helpers (sm_103a-only) ----------------
__device__ __forceinline__ unsigned smem_u32(const void* p) {
    unsigned a; asm("{ .reg .u64 t; cvta.to.shared.u64 t, %1; cvt.u32.u64 %0, t; }" : "=r"(a) : "l"(p));
    return a;
}
__device__ __forceinline__ bool elect_one() {
    unsigned p;
    asm volatile("{\n\t.reg .pred P;\n\telect.sync _|P, 0xFFFFFFFF;\n\tselp.b32 %0, 1, 0, P;\n\t}" : "=r"(p));
    return p != 0;
}
__device__ __forceinline__ void tc_alloc(unsigned dst_smem, unsigned ncols) {
    asm volatile("tcgen05.alloc.cta_group::1.sync.aligned.shared::cta.b32 [%0], %1;"
                 :: "r"(dst_smem), "r"(ncols) : "memory");
}
__device__ __forceinline__ void tc_dealloc(unsigned tmem, unsigned ncols) {
    asm volatile("tcgen05.dealloc.cta_group::1.sync.aligned.b32 %0, %1;" :: "r"(tmem), "r"(ncols));
}
__device__ __forceinline__ void mbar_init(unsigned mbar, unsigned cnt) {
    asm volatile("mbarrier.init.shared.b64 [%0], %1;" :: "r"(mbar), "r"(cnt) : "memory");
}
__device__ __forceinline__ void mbar_wait(unsigned mbar, unsigned parity) {
    asm volatile(
        "{\n\t.reg .pred P;\n\t"
        "WL%=:\n\t"
        "mbarrier.try_wait.parity.shared.b64 P, [%0], %1, 0x989680;\n\t"
        "@P bra WD%=;\n\t"
        "bra WL%=;\n\t"
        "WD%=:\n\t}"
        :: "r"(mbar), "r"(parity) : "memory");
}
__device__ __forceinline__ void mbar_expect_tx(unsigned mbar, unsigned bytes) {
    asm volatile("mbarrier.arrive.expect_tx.shared.b64 _, [%0], %1;"
                 :: "r"(mbar), "r"(bytes) : "memory");
}
__device__ __forceinline__ void bulk_g2s(unsigned dst, const void* src, unsigned bytes, unsigned mbar) {
    asm volatile("cp.async.bulk.shared::cluster.global.mbarrier::complete_tx::bytes [%0], [%1], %2, [%3];"
                 :: "r"(dst), "l"(src), "r"(bytes), "r"(mbar) : "memory");
}
__device__ __forceinline__ void tc_commit(unsigned mbar) {
    asm volatile("tcgen05.commit.cta_group::1.mbarrier::arrive::one.shared::cluster.b64 [%0];"
                 :: "r"(mbar) : "memory");
}
__device__ __forceinline__ void mma_f16(unsigned d, u64 adesc, u64 bdesc, unsigned idesc, unsigned en) {
    asm volatile(
        "{\n\t.reg .pred p;\n\tsetp.ne.u32 p, %4, 0;\n\t"
        "tcgen05.mma.cta_group::1.kind::f16 [%0], %1, %2, %3, {%5, %5, %5, %5}, p;\n\t}"
        :: "r"(d), "l"(adesc), "l"(bdesc), "r"(idesc), "r"(en), "r"(0u) : "memory");
}
__device__ __forceinline__ void ldtm32(unsigned* r, unsigned addr) {
    asm volatile(
        "tcgen05.ld.sync.aligned.32x32b.x32.b32 "
        "{%0, %1, %2, %3, %4, %5, %6, %7, %8, %9, %10, %11, %12, %13, %14, %15, "
        " %16, %17, %18, %19, %20, %21, %22, %23, %24, %25, %26, %27, %28, %29, %30, %31}, [%32];"
        : "=r"(r[0]),  "=r"(r[1]),  "=r"(r[2]),  "=r"(r[3]),
          "=r"(r[4]),  "=r"(r[5]),  "=r"(r[6]),  "=r"(r[7]),
          "=r"(r[8]),  "=r"(r[9]),  "=r"(r[10]), "=r"(r[11]),
          "=r"(r[12]), "=r"(r[13]), "=r"(r[14]), "=r"(r[15]),
          "=r"(r[16]), "=r"(r[17]), "=r"(r[18]), "=r"(r[19]),
          "=r"(r[20]), "=r"(r[21]), "=r"(r[22]), "=r"(r[23]),
          "=r"(r[24]), "=r"(r[25]), "=r"(r[26]), "=r"(r[27]),
          "=r"(r[28]), "=r"(r[29]), "=r"(r[30]), "=r"(r[31])
        : "r"(addr));
}
__device__ __forceinline__ void tc_wait_ld()  { asm volatile("tcgen05.wait::ld.sync.aligned;" ::: "memory"); }
__device__ __forceinline__ u64 make_desc(unsigned addr) {
    return ((u64)2 << 61) | ((u64)1 << 46) | ((u64)64 << 32) | ((u64)1 << 16)
         | (u64)((addr >> 4) & 0x3FFF);
}
#endif // TC_OK

// idesc: F32 accum, BF16 x BF16, M=128, N=192
#define MMA_IDESC 0x8300490u

// ---------------------------------------------------------------------------
// Region weight prep: w[g][co][ci][3][3] fp32 ->
//   blob[(g*9+kk)*3+cc] = [ hi tile 192x64 SW128-swizzled | lo tile ]   (bf16)
// ---------------------------------------------------------------------------
__global__ void prep_region_blob(const float* __restrict__ w, __nv_bfloat16* __restrict__ blob, int total)
{
    int idx = blockIdx.x * blockDim.x + threadIdx.x;
    if (idx >= total) return;
    int j  = idx & 63;
    int t  = idx >> 6;
    int co = t % 192;  t /= 192;
    int cc = t % 3;    t /= 3;
    int kk = t % 9;
    int g  = t / 9;
    int ci = cc*64 + j, ky = kk/3, kx = kk%3;
    float v = w[((((size_t)g*192 + co)*192 + ci)*3 + ky)*3 + kx];
    __nv_bfloat16 h = __float2bfloat16(v);
    __nv_bfloat16 l = __float2bfloat16(v - __bfloat162float(h));
    int off = co*128 + j*2;
    off ^= (off >> 3) & 0x70;                 // SW128 swizzle
    size_t base = ((size_t)((g*9 + kk)*3 + cc)) * 24576;
    blob[base + off/2]         = h;
    blob[base + 12288 + off/2] = l;
}

__global__ void transpose_conv_w(const float* __restrict__ w, float* __restrict__ wT, int CO, int total)
{
    int idx = blockIdx.x * blockDim.x + threadIdx.x;
    if (idx >= total) return;
    int k  = idx & 3;
    int t  = idx >> 2;
    int co = t % CO;
    int ci = t / CO;
    wT[idx] = w[(((size_t)co*192) + ci)*4 + k];
}

// ---------------------------------------------------------------------------
// conv1: x(64,3,224,224) * w(192,3,4,4) stride4 VALID -> bn -> gelu -> bufA
// ---------------------------------------------------------------------------
__global__ __launch_bounds__(192) void conv1_kernel(
    const float* __restrict__ x, const float* __restrict__ w,
    const float* __restrict__ bg, const float* __restrict__ bb,
    const float* __restrict__ bm, const float* __restrict__ bv)
{
    const int oh = blockIdx.x;
    const int b  = blockIdx.y;
    const int co = threadIdx.x;
    __shared__ float s_in[3*4*224];

    for (int i = co; i < 3*4*224; i += 192) {
        int ci = i / (4*224);
        int r  = (i / 224) & 3;
        int c  = i % 224;
        s_in[i] = x[(((size_t)b*3 + ci)*224 + (oh*4 + r))*224 + c];
    }
    float wreg[48];
    #pragma unroll
    for (int k = 0; k < 48; ++k) wreg[k] = w[co*48 + k];
    const float inv  = bg[co] * rsqrtf(bv[co] + EPS);
    const float beta = bb[co] - bm[co]*inv;
    __syncthreads();

    float* outp = &g_bufA[(((size_t)b*192 + co)*56 + oh)*56];
    for (int ow = 0; ow < 56; ++ow) {
        float acc = 0.f;
        #pragma unroll
        for (int ci = 0; ci < 3; ++ci)
            #pragma unroll
            for (int r = 0; r < 4; ++r)
                #pragma unroll
                for (int c = 0; c < 4; ++c)
                    acc = fmaf(wreg[(ci*4+r)*4+c], s_in[(ci*4+r)*224 + ow*4 + c], acc);
        outp[ow] = gelu_exact(acc*inv + beta);
    }
}

// ---------------------------------------------------------------------------
// region_mma v2: tcgen05 bf16-split GEMM with TMA-fed, double-buffered B.
// CTA = (b-pair, g). D[128 pos, 192 co] fp32 in TMEM.
// Per iteration (27 = 9 offsets x 3 ci-chunks): A gathered by threads (32 KB),
// B arrives via cp.async.bulk into the alternate buffer during the MMAs.
// ---------------------------------------------------------------------------
#define OF_TMEM   0
#define OF_MBAR   8          /* mma completion */
#define OF_TBAR0  16         /* tma buffer 0 */
#define OF_TBAR1  24         /* tma buffer 1 */
#define OF_INV    32
#define OF_BETA   (32 + 768)
#define OF_AHI    2048
#define OF_ALO    18432
#define OF_B0     34816      /* [hi 24576 | lo 24576] */
#define OF_B1     83968
#define OF_PL     133120     /* 4 planes x (49 rows x 400 B) */
#define PL_STRIDE 19600
#define REGION_SMEM 211520

__global__ __launch_bounds__(256, 1)
void region_mma(const __nv_bfloat16* __restrict__ blob,
                const float* __restrict__ bg, const float* __restrict__ bb,
                const float* __restrict__ bm, const float* __restrict__ bv,
                int H)   // 56 or 28
{
#if TC_OK
    extern __shared__ char smem[];
    float* buf = (H == 56) ? g_bufA : g_bufB;
    const int GW = H / 7;
    const int b0 = blockIdx.x * 2;
    const int g  = blockIdx.y;
    const int base_h = (g / GW) * 7;
    const int base_w = (g % GW) * 7;
    const int t = threadIdx.x, wid = t >> 5, lane = t & 31;
    const unsigned sbase = smem_u32(smem);
    const char* bsrc = (const char*)(blob + (size_t)g * 27 * 24576);  // 49152 B per iter

    if (wid == 0) tc_alloc(sbase + OF_TMEM, 256);

    // BN coefficient tables
    if (t < 192) {
        int gc = g*192 + t;
        float inv = bg[gc] * rsqrtf(bv[gc] + EPS);
        ((float*)(smem + OF_INV))[t]  = inv;
        ((float*)(smem + OF_BETA))[t] = bb[gc] - bm[gc]*inv;
    }
    if (t == 0) {
        mbar_init(sbase + OF_MBAR, 1);
        mbar_init(sbase + OF_TBAR0, 1);
        mbar_init(sbase + OF_TBAR1, 1);
    }

    // zero the permanent pad rows of A tiles (rows 49-63, 113-127; hi and lo)
    for (int u = t; u < 480; u += 256) {
        int set = u / 240, v = u % 240, rr = v / 8, j = v % 8;
        int m = (rr < 15) ? (49 + rr) : (113 - 15 + rr);
        int off = m*128 + j*16;  off ^= (off >> 3) & 0x70;
        *(float4*)(smem + (set ? OF_ALO : OF_AHI) + off) = make_float4(0.f, 0.f, 0.f, 0.f);
    }
    __syncthreads();   // mbarriers + pads visible

    // kick off B(0), B(1) via TMA while we stage the input planes
    if (t == 0) {
        mbar_expect_tx(sbase + OF_TBAR0, 49152);
        bulk_g2s(sbase + OF_B0, bsrc,          49152, sbase + OF_TBAR0);
        mbar_expect_tx(sbase + OF_TBAR1, 49152);
        bulk_g2s(sbase + OF_B1, bsrc + 49152,  49152, sbase + OF_TBAR1);
    }

    // bf16 hi/lo planes of the two input tiles: plane[p(49)][ci(192)], 400 B rows
    for (int i = t; i < 2*192*49; i += 256) {
        int ow = i % 7, oh = (i/7) % 7, ci = (i/49) % 192, bl = i / 9408;
        float v = buf[(((size_t)(b0 + bl)*192 + ci)*H + base_h + oh)*H + base_w + ow];
        __nv_bfloat16 h = __float2bfloat16(v);
        __nv_bfloat16 l = __float2bfloat16(v - __bfloat162float(h));
        int p = oh*7 + ow;
        *(__nv_bfloat16*)(smem + OF_PL + (bl*2 + 0)*PL_STRIDE + p*400 + ci*2) = h;
        *(__nv_bfloat16*)(smem + OF_PL + (bl*2 + 1)*PL_STRIDE + p*400 + ci*2) = l;
    }
    __syncthreads();

    unsigned tmem;
    asm volatile("ld.shared.b32 %0, [%1];" : "=r"(tmem) : "r"(sbase + OF_TMEM));

    const u64 dAhi = make_desc(sbase + OF_AHI);
    const u64 dAlo = make_desc(sbase + OF_ALO);
    const u64 dB[2] = { make_desc(sbase + OF_B0), make_desc(sbase + OF_B1) };

    #pragma unroll 1
    for (int it = 0; it < 27; ++it) {
        // wait for previous MMAs (A + the other B buffer become reusable)
        if (it > 0) mbar_wait(sbase + OF_MBAR, (unsigned)((it - 1) & 1));

        // refill the alternate B buffer for it+1 (its consumer mma(it-1) is done)
        if (it >= 1 && it + 1 < 27) {
            if (t == 0) {
                unsigned nb = (it + 1) & 1;
                unsigned tb = sbase + (nb ? OF_TBAR1 : OF_TBAR0);
                mbar_expect_tx(tb, 49152);
                bulk_g2s(sbase + (nb ? OF_B1 : OF_B0), bsrc + (size_t)(it + 1)*49152, 49152, tb);
            }
        }

        // A: gather shifted plane rows into SW128 tiles (hi and lo)
        const int ky = (it/3) / 3, kx = (it/3) % 3, cc = it % 3;
        #pragma unroll
        for (int u = t; u < 2048; u += 256) {
            int set = u >> 10, v = u & 1023, m = v >> 3, j = v & 7;
            int p = m & 63, bl = m >> 6;
            if (p >= 49) continue;                        // permanent zero rows
            float4 val = make_float4(0.f, 0.f, 0.f, 0.f);
            int oh = p/7 + ky - 1, ow = p%7 + kx - 1;
            if (oh >= 0 && oh < 7 && ow >= 0 && ow < 7)
                val = *(const float4*)(smem + OF_PL + (bl*2 + set)*PL_STRIDE
                                       + (oh*7 + ow)*400 + cc*128 + j*16);
            int off = m*128 + j*16;  off ^= (off >> 3) & 0x70;
            *(float4*)(smem + (set ? OF_ALO : OF_AHI) + off) = val;
        }

        asm volatile("fence.proxy.async.shared::cta;" ::: "memory");
        __syncthreads();

        if (wid == 0 && elect_one()) {
            const unsigned bsel = it & 1;
            // B(it) must have landed
            mbar_wait(sbase + (bsel ? OF_TBAR1 : OF_TBAR0), (unsigned)((it >> 1) & 1));
            const u64 dBhi = dB[bsel];
            const u64 dBlo = dB[bsel] + (24576 >> 4);     // +24576 B in 16B units
            #pragma unroll
            for (int ks = 0; ks < 4; ++ks)
                mma_f16(tmem, dAhi + ks*2, dBhi + ks*2, MMA_IDESC, (it == 0 && ks == 0) ? 0u : 1u);
            #pragma unroll
            for (int ks = 0; ks < 4; ++ks)
                mma_f16(tmem, dAhi + ks*2, dBlo + ks*2, MMA_IDESC, 1u);
            #pragma unroll
            for (int ks = 0; ks < 4; ++ks)
                mma_f16(tmem, dAlo + ks*2, dBhi + ks*2, MMA_IDESC, 1u);
            tc_commit(sbase + OF_MBAR);
        }
    }
    mbar_wait(sbase + OF_MBAR, 0u);                       // iter 26: parity 0
    asm volatile("tcgen05.fence::after_thread_sync;" ::: "memory");

    // Epilogue: warps 0-3 read D rows (lanes = positions), BN+GELU+residual, write back
    if (wid < 4) {
        const int m = wid*32 + lane, p = m & 63, bl = m >> 6;
        const bool live = (p < 49);
        const float* sinv  = (const float*)(smem + OF_INV);
        const float* sbeta = (const float*)(smem + OF_BETA);
        float* dstb = buf + ((size_t)(b0 + bl)*192) * H * H;
        const size_t pix = (size_t)(base_h + p/7)*H + base_w + p%7;
        #pragma unroll 1
        for (int c0 = 0; c0 < 192; c0 += 32) {
            unsigned r[32];
            ldtm32(r, tmem + c0);
            tc_wait_ld();
            if (live) {
                #pragma unroll
                for (int c = 0; c < 32; ++c) {
                    int co = c0 + c;
                    float a = __uint_as_float(r[c]);
                    float y = gelu_exact(a*sinv[co] + sbeta[co]);
                    float rh = __bfloat162float(*(const __nv_bfloat16*)
                        (smem + OF_PL + (bl*2 + 0)*PL_STRIDE + p*400 + co*2));
                    float rl = __bfloat162float(*(const __nv_bfloat16*)
                        (smem + OF_PL + (bl*2 + 1)*PL_STRIDE + p*400 + co*2));
                    dstb[(size_t)co*H*H + pix] = y + rh + rl;
                }
            }
        }
    }
    __syncthreads();
    if (wid == 0) tc_dealloc(tmem, 256);
#endif // TC_OK — fallback pass compiles an empty body; GB300 runs the sm_103a cubin
}

// ---------------------------------------------------------------------------
// conv2: bufA * wT2[ci][co][k] stride2 -> bn -> gelu -> bufB
// ---------------------------------------------------------------------------
__global__ __launch_bounds__(192) void conv2_kernel(
    const float* __restrict__ wT,
    const float* __restrict__ bg, const float* __restrict__ bb,
    const float* __restrict__ bm, const float* __restrict__ bv)
{
    const int q  = blockIdx.x;
    const int oh = blockIdx.y;
    const int b  = blockIdx.z;
    const int co = threadIdx.x;
    __shared__ float s_in[192*2*28];

    for (int i = co; i < 192*2*28; i += 192) {
        int ci = i / 56, r = (i/28) & 1, c = i % 28;
        s_in[i] = g_bufA[(((size_t)b*192 + ci)*56 + 2*oh + r)*56 + q*28 + c];
    }
    __syncthreads();

    float acc[14];
    #pragma unroll
    for (int j = 0; j < 14; ++j) acc[j] = 0.f;

    const float4* w4 = reinterpret_cast<const float4*>(wT) + co;
    for (int ci = 0; ci < 192; ++ci) {
        const float4 wv = w4[ci*192];
        const float4* r0 = reinterpret_cast<const float4*>(&s_in[ci*56]);
        const float4* r1 = reinterpret_cast<const float4*>(&s_in[ci*56 + 28]);
        #pragma unroll
        for (int p = 0; p < 7; ++p) {
            float4 a = r0[p], c = r1[p];
            acc[2*p]   = fmaf(wv.x, a.x, fmaf(wv.y, a.y, fmaf(wv.z, c.x, fmaf(wv.w, c.y, acc[2*p]))));
            acc[2*p+1] = fmaf(wv.x, a.z, fmaf(wv.y, a.w, fmaf(wv.z, c.z, fmaf(wv.w, c.w, acc[2*p+1]))));
        }
    }
    const float inv  = bg[co] * rsqrtf(bv[co] + EPS);
    const float beta = bb[co] - bm[co]*inv;
    float* op = &g_bufB[(((size_t)b*192 + co)*28 + oh)*28 + q*14];
    #pragma unroll
    for (int ow = 0; ow < 14; ++ow) op[ow] = gelu_exact(acc[ow]*inv + beta);
}

// ---------------------------------------------------------------------------
// conv3: bufB * wT3[ci][co][k] stride2 -> bn -> transposed write (B,196,768)
// ---------------------------------------------------------------------------
__global__ __launch_bounds__(768) void conv3_kernel(
    const float* __restrict__ wT,
    const float* __restrict__ bg, const float* __restrict__ bb,
    const float* __restrict__ bm, const float* __restrict__ bv,
    float* __restrict__ out)
{
    const int oh = blockIdx.x;
    const int b  = blockIdx.y;
    const int co = threadIdx.x;
    __shared__ float s_in[192*2*28];

    for (int i = co; i < 192*2*28; i += 768) {
        int ci = i / 56, r = (i/28) & 1, c = i % 28;
        s_in[i] = g_bufB[(((size_t)b*192 + ci)*28 + 2*oh + r)*28 + c];
    }
    __syncthreads();

    float acc[14];
    #pragma unroll
    for (int j = 0; j < 14; ++j) acc[j] = 0.f;

    const float4* w4 = reinterpret_cast<const float4*>(wT) + co;
    for (int ci = 0; ci < 192; ++ci) {
        const float4 wv = w4[ci*768];
        const float4* r0 = reinterpret_cast<const float4*>(&s_in[ci*56]);
        const float4* r1 = reinterpret_cast<const float4*>(&s_in[ci*56 + 28]);
        #pragma unroll
        for (int p = 0; p < 7; ++p) {
            float4 a = r0[p], c = r1[p];
            acc[2*p]   = fmaf(wv.x, a.x, fmaf(wv.y, a.y, fmaf(wv.z, c.x, fmaf(wv.w, c.y, acc[2*p]))));
            acc[2*p+1] = fmaf(wv.x, a.z, fmaf(wv.y, a.w, fmaf(wv.z, c.z, fmaf(wv.w, c.w, acc[2*p+1]))));
        }
    }
    const float inv  = bg[co] * rsqrtf(bv[co] + EPS);
    const float beta = bb[co] - bm[co]*inv;
    #pragma unroll
    for (int ow = 0; ow < 14; ++ow)
        out[((size_t)b*196 + oh*14 + ow)*768 + co] = acc[ow]*inv + beta;
}

// ---------------------------------------------------------------------------
extern "C" void kernel_launch(void* const* d_in, const int* in_sizes, int n_in,
                              void* d_out, int out_size)
{
    const float* x       = (const float*)d_in[0];
    const float* c1w     = (const float*)d_in[1];
    const float* b1g = (const float*)d_in[2],  *b1b = (const float*)d_in[3];
    const float* b1m = (const float*)d_in[4],  *b1v = (const float*)d_in[5];
    const float* r1w     = (const float*)d_in[6];
    const float* r1g = (const float*)d_in[7],  *r1b = (const float*)d_in[8];
    const float* r1m = (const float*)d_in[9],  *r1v = (const float*)d_in[10];
    const float* c2w     = (const float*)d_in[11];
    const float* b2g = (const float*)d_in[12], *b2b = (const float*)d_in[13];
    const float* b2m = (const float*)d_in[14], *b2v = (const float*)d_in[15];
    const float* r2w     = (const float*)d_in[16];
    const float* r2g = (const float*)d_in[17], *r2b = (const float*)d_in[18];
    const float* r2m = (const float*)d_in[19], *r2v = (const float*)d_in[20];
    const float* c3w     = (const float*)d_in[21];
    const float* b3g = (const float*)d_in[22], *b3b = (const float*)d_in[23];
    const float* b3m = (const float*)d_in[24], *b3v = (const float*)d_in[25];
    float* out = (float*)d_out;

    __nv_bfloat16 *blob1, *blob2;
    float *c2wT, *c3wT;
    cudaGetSymbolAddress((void**)&blob1, g_blob1);
    cudaGetSymbolAddress((void**)&blob2, g_blob2);
    cudaGetSymbolAddress((void**)&c2wT, g_c2wT);
    cudaGetSymbolAddress((void**)&c3wT, g_c3wT);

    {   // weight prep
        int t1 = 64*9*3*192*64;
        prep_region_blob<<<(t1 + 255)/256, 256>>>(r1w, blob1, t1);
        int t2 = 16*9*3*192*64;
        prep_region_blob<<<(t2 + 255)/256, 256>>>(r2w, blob2, t2);
        int t3 = 192*192*4;
        transpose_conv_w<<<(t3 + 255)/256, 256>>>(c2w, c2wT, 192, t3);
        int t4 = 192*768*4;
        transpose_conv_w<<<(t4 + 255)/256, 256>>>(c3w, c3wT, 768, t4);
    }

    cudaFuncSetAttribute(region_mma, cudaFuncAttributeMaxDynamicSharedMemorySize, REGION_SMEM);

    conv1_kernel<<<dim3(56, 64), 192>>>(x, c1w, b1g, b1b, b1m, b1v);
    region_mma<<<dim3(32, 64), 256, REGION_SMEM>>>(blob1, r1g, r1b, r1m, r1v, 56);
    conv2_kernel<<<dim3(2, 28, 64), 192>>>(c2wT, b2g, b2b, b2m, b2v);
    region_mma<<<dim3(32, 16), 256, REGION_SMEM>>>(blob2, r2g, r2b, r2m, r2v, 28);
    conv3_kernel<<<dim3(14, 64), 768>>>(c3wT, b3g, b3b, b3m, b3v, out);
}

// round 13
// speedup vs baseline: 2.7788x; 1.6185x over previous
#include <cuda_runtime.h>
#include <cuda_bf16.h>
#include <math.h>

#define EPS 1e-5f
typedef unsigned long long u64;

// tcgen05 only exists on the arch-accelerated target; the fatbin also builds a
// plain compute_103 pass where these instructions are illegal.
#if !defined(__CUDA_ARCH__) || defined(__CUDA_ARCH_FEAT_SM103_ALL) || defined(__CUDA_ARCH_FEAT_SM100_ALL) || defined(__CUDA_ARCH_FEAT_SM101_ALL)
#define TC_OK 1
#else
#define TC_OK 0
#endif

// Scratch (device globals — no runtime allocation). ALL intermediates NHWC.
__device__ float g_bufA[(size_t)64*56*56*192];         // conv1 out (NHWC), region1 in-place
__device__ float g_bufB[(size_t)64*28*28*192];         // conv2 out (NHWC), region2 in-place
__device__ __nv_bfloat16 g_blob1[(size_t)64*27*24576]; // r1 W: per (g,kk,cc): [hi 192x64 SW128 | lo]
__device__ __nv_bfloat16 g_blob2[(size_t)16*27*24576]; // r2 likewise
__device__ __nv_bfloat16 g_blob2c[(size_t)12*24576];   // conv2 W: per (k,cc): [hi|lo]
__device__ __nv_bfloat16 g_blob3c[(size_t)4*12*24576]; // conv3 W: per (nh,k,cc): [hi|lo]

__device__ __forceinline__ float gelu_exact(float x) {
    return 0.5f * x * (1.0f + erff(x * 0.70710678118654752f));
}
__device__ __forceinline__ void hl_split(float v, __nv_bfloat16& h, __nv_bfloat16& l) {
    h = __float2bfloat16(v);
    l = __float2bfloat16(v - __bfloat162float(h));
}

#if TC_OK
// ---------------- tcgen05 / TMA / mbarrier PTX helpers ----------------
__device__ __forceinline__ unsigned smem_u32(const void* p) {
    unsigned a; asm("{ .reg .u64 t; cvta.to.shared.u64 t, %1; cvt.u32.u64 %0, t; }" : "=r"(a) : "l"(p));
    return a;
}
__device__ __forceinline__ bool elect_one() {
    unsigned p;
    asm volatile("{\n\t.reg .pred P;\n\telect.sync _|P, 0xFFFFFFFF;\n\tselp.b32 %0, 1, 0, P;\n\t}" : "=r"(p));
    return p != 0;
}
__device__ __forceinline__ void tc_alloc(unsigned dst_smem, unsigned ncols) {
    asm volatile("tcgen05.alloc.cta_group::1.sync.aligned.shared::cta.b32 [%0], %1;"
                 :: "r"(dst_smem), "r"(ncols) : "memory");
}
__device__ __forceinline__ void tc_dealloc(unsigned tmem, unsigned ncols) {
    asm volatile("tcgen05.dealloc.cta_group::1.sync.aligned.b32 %0, %1;" :: "r"(tmem), "r"(ncols));
}
__device__ __forceinline__ void mbar_init(unsigned mbar, unsigned cnt) {
    asm volatile("mbarrier.init.shared.b64 [%0], %1;" :: "r"(mbar), "r"(cnt) : "memory");
}
__device__ __forceinline__ void mbar_wait(unsigned mbar, unsigned parity) {
    asm volatile(
        "{\n\t.reg .pred P;\n\t"
        "WL%=:\n\t"
        "mbarrier.try_wait.parity.shared.b64 P, [%0], %1, 0x989680;\n\t"
        "@P bra WD%=;\n\t"
        "bra WL%=;\n\t"
        "WD%=:\n\t}"
        :: "r"(mbar), "r"(parity) : "memory");
}
__device__ __forceinline__ void mbar_expect_tx(unsigned mbar, unsigned bytes) {
    asm volatile("mbarrier.arrive.expect_tx.shared.b64 _, [%0], %1;"
                 :: "r"(mbar), "r"(bytes) : "memory");
}
__device__ __forceinline__ void bulk_g2s(unsigned dst, const void* src, unsigned bytes, unsigned mbar) {
    asm volatile("cp.async.bulk.shared::cluster.global.mbarrier::complete_tx::bytes [%0], [%1], %2, [%3];"
                 :: "r"(dst), "l"(src), "r"(bytes), "r"(mbar) : "memory");
}
__device__ __forceinline__ void tc_commit(unsigned mbar) {
    asm volatile("tcgen05.commit.cta_group::1.mbarrier::arrive::one.shared::cluster.b64 [%0];"
                 :: "r"(mbar) : "memory");
}
__device__ __forceinline__ void mma_f16(unsigned d, u64 adesc, u64 bdesc, unsigned idesc, unsigned en) {
    asm volatile(
        "{\n\t.reg .pred p;\n\tsetp.ne.u32 p, %4, 0;\n\t"
        "tcgen05.mma.cta_group::1.kind::f16 [%0], %1, %2, %3, {%5, %5, %5, %5}, p;\n\t}"
        :: "r"(d), "l"(adesc), "l"(bdesc), "r"(idesc), "r"(en), "r"(0u) : "memory");
}
__device__ __forceinline__ void ldtm32(unsigned* r, unsigned addr) {
    asm volatile(
        "tcgen05.ld.sync.aligned.32x32b.x32.b32 "
        "{%0, %1, %2, %3, %4, %5, %6, %7, %8, %9, %10, %11, %12, %13, %14, %15, "
        " %16, %17, %18, %19, %20, %21, %22, %23, %24, %25, %26, %27, %28, %29, %30, %31}, [%32];"
        : "=r"(r[0]),  "=r"(r[1]),  "=r"(r[2]),  "=r"(r[3]),
          "=r"(r[4]),  "=r"(r[5]),  "=r"(r[6]),  "=r"(r[7]),
          "=r"(r[8]),  "=r"(r[9]),  "=r"(r[10]), "=r"(r[11]),
          "=r"(r[12]), "=r"(r[13]), "=r"(r[14]), "=r"(r[15]),
          "=r"(r[16]), "=r"(r[17]), "=r"(r[18]), "=r"(r[19]),
          "=r"(r[20]), "=r"(r[21]), "=r"(r[22]), "=r"(r[23]),
          "=r"(r[24]), "=r"(r[25]), "=r"(r[26]), "=r"(r[27]),
          "=r"(r[28]), "=r"(r[29]), "=r"(r[30]), "=r"(r[31])
        : "r"(addr));
}
__device__ __forceinline__ void tc_wait_ld()  { asm volatile("tcgen05.wait::ld.sync.aligned;" ::: "memory"); }
__device__ __forceinline__ u64 make_desc(unsigned addr) {
    return ((u64)2 << 61) | ((u64)1 << 46) | ((u64)64 << 32) | ((u64)1 << 16)
         | (u64)((addr >> 4) & 0x3FFF);
}
#endif // TC_OK

// idesc: F32 accum, BF16 x BF16, M=128, N=192
#define MMA_IDESC 0x8300490u

// ---------------------------------------------------------------------------
// Weight prep
// ---------------------------------------------------------------------------
__global__ void prep_region_blob(const float* __restrict__ w, __nv_bfloat16* __restrict__ blob, int total)
{
    int idx = blockIdx.x * blockDim.x + threadIdx.x;
    if (idx >= total) return;
    int j  = idx & 63;
    int t  = idx >> 6;
    int co = t % 192;  t /= 192;
    int cc = t % 3;    t /= 3;
    int kk = t % 9;
    int g  = t / 9;
    int ci = cc*64 + j, ky = kk/3, kx = kk%3;
    float v = w[((((size_t)g*192 + co)*192 + ci)*3 + ky)*3 + kx];
    __nv_bfloat16 h, l; hl_split(v, h, l);
    int off = co*128 + j*2;
    off ^= (off >> 3) & 0x70;                 // SW128 swizzle
    size_t base = ((size_t)((g*9 + kk)*3 + cc)) * 24576;
    blob[base + off/2]         = h;
    blob[base + 12288 + off/2] = l;
}

// conv weights w[CO,192,2,2] -> blob[(nh*4+k)*3+cc] = [hi 192x64 SW128 | lo]
__global__ void prep_conv_blob(const float* __restrict__ w, __nv_bfloat16* __restrict__ blob, int CO, int total)
{
    int idx = blockIdx.x * blockDim.x + threadIdx.x;
    if (idx >= total) return;
    int j  = idx & 63;
    int t  = idx >> 6;
    int co = t % CO;  t /= CO;
    int k  = t / 3;
    int cc = t % 3;
    int ci = cc*64 + j;
    float v = w[(((size_t)co*192) + ci)*4 + k];
    __nv_bfloat16 h, l; hl_split(v, h, l);
    int nh = co / 192, cop = co % 192;
    int off = cop*128 + j*2;
    off ^= (off >> 3) & 0x70;
    size_t base = ((size_t)((nh*4 + k)*3 + cc)) * 24576;
    blob[base + off/2]         = h;
    blob[base + 12288 + off/2] = l;
}

// ---------------------------------------------------------------------------
// conv1: x(64,3,224,224) NCHW * w(192,3,4,4) s4 VALID -> bn -> gelu -> bufA NHWC
// ---------------------------------------------------------------------------
__global__ __launch_bounds__(192) void conv1_kernel(
    const float* __restrict__ x, const float* __restrict__ w,
    const float* __restrict__ bg, const float* __restrict__ bb,
    const float* __restrict__ bm, const float* __restrict__ bv)
{
    const int oh = blockIdx.x;
    const int b  = blockIdx.y;
    const int co = threadIdx.x;
    __shared__ float s_in[3*4*224];

    for (int i = co; i < 3*4*224; i += 192) {
        int ci = i / (4*224);
        int r  = (i / 224) & 3;
        int c  = i % 224;
        s_in[i] = x[(((size_t)b*3 + ci)*224 + (oh*4 + r))*224 + c];
    }
    float wreg[48];
    #pragma unroll
    for (int k = 0; k < 48; ++k) wreg[k] = w[co*48 + k];
    const float inv  = bg[co] * rsqrtf(bv[co] + EPS);
    const float beta = bb[co] - bm[co]*inv;
    __syncthreads();

    float* outp = &g_bufA[(((size_t)b*56 + oh)*56)*192 + co];
    for (int ow = 0; ow < 56; ++ow) {
        float acc = 0.f;
        #pragma unroll
        for (int ci = 0; ci < 3; ++ci)
            #pragma unroll
            for (int r = 0; r < 4; ++r)
                #pragma unroll
                for (int c = 0; c < 4; ++c)
                    acc = fmaf(wreg[(ci*4+r)*4+c], s_in[(ci*4+r)*224 + ow*4 + c], acc);
        outp[(size_t)ow*192] = gelu_exact(acc*inv + beta);   // coalesced over co
    }
}

// ---------------------------------------------------------------------------
// region_mma (NHWC): tcgen05 bf16-split GEMM, TMA-fed double-buffered B.
// ---------------------------------------------------------------------------
#define OF_TMEM   0
#define OF_MBAR   8
#define OF_TBAR0  16
#define OF_TBAR1  24
#define OF_INV    32
#define OF_BETA   (32 + 768)
#define OF_AHI    2048
#define OF_ALO    18432
#define OF_B0     34816
#define OF_B1     83968
#define OF_PL     133120
#define PL_STRIDE 19600
#define REGION_SMEM 211520

__global__ __launch_bounds__(256, 1)
void region_mma(const __nv_bfloat16* __restrict__ blob,
                const float* __restrict__ bg, const float* __restrict__ bb,
                const float* __restrict__ bm, const float* __restrict__ bv,
                int H)   // 56 or 28
{
#if TC_OK
    extern __shared__ char smem[];
    float* buf = (H == 56) ? g_bufA : g_bufB;
    const int GW = H / 7;
    const int b0 = blockIdx.x * 2;
    const int g  = blockIdx.y;
    const int base_h = (g / GW) * 7;
    const int base_w = (g % GW) * 7;
    const int t = threadIdx.x, wid = t >> 5, lane = t & 31;
    const unsigned sbase = smem_u32(smem);
    const char* bsrc = (const char*)(blob + (size_t)g * 27 * 24576);

    if (wid == 0) tc_alloc(sbase + OF_TMEM, 256);

    if (t < 192) {
        int gc = g*192 + t;
        float inv = bg[gc] * rsqrtf(bv[gc] + EPS);
        ((float*)(smem + OF_INV))[t]  = inv;
        ((float*)(smem + OF_BETA))[t] = bb[gc] - bm[gc]*inv;
    }
    if (t == 0) {
        mbar_init(sbase + OF_MBAR, 1);
        mbar_init(sbase + OF_TBAR0, 1);
        mbar_init(sbase + OF_TBAR1, 1);
    }
    // zero permanent pad rows of A tiles (rows 49-63, 113-127)
    for (int u = t; u < 480; u += 256) {
        int set = u / 240, v = u % 240, rr = v / 8, j = v % 8;
        int m = (rr < 15) ? (49 + rr) : (113 - 15 + rr);
        int off = m*128 + j*16;  off ^= (off >> 3) & 0x70;
        *(float4*)(smem + (set ? OF_ALO : OF_AHI) + off) = make_float4(0.f, 0.f, 0.f, 0.f);
    }
    __syncthreads();

    if (t == 0) {
        mbar_expect_tx(sbase + OF_TBAR0, 49152);
        bulk_g2s(sbase + OF_B0, bsrc,          49152, sbase + OF_TBAR0);
        mbar_expect_tx(sbase + OF_TBAR1, 49152);
        bulk_g2s(sbase + OF_B1, bsrc + 49152,  49152, sbase + OF_TBAR1);
    }

    // stage input planes: NHWC rows (coalesced 768B). plane[p][ci], hi/lo.
    for (int i = t; i < 2*49*192; i += 256) {
        int ci = i % 192, p = (i/192) % 49, bl = i / (49*192);
        float v = buf[(((size_t)(b0 + bl)*H + base_h + p/7)*H + base_w + p%7)*192 + ci];
        __nv_bfloat16 h, l; hl_split(v, h, l);
        *(__nv_bfloat16*)(smem + OF_PL + (bl*2 + 0)*PL_STRIDE + p*400 + ci*2) = h;
        *(__nv_bfloat16*)(smem + OF_PL + (bl*2 + 1)*PL_STRIDE + p*400 + ci*2) = l;
    }
    __syncthreads();

    unsigned tmem;
    asm volatile("ld.shared.b32 %0, [%1];" : "=r"(tmem) : "r"(sbase + OF_TMEM));

    const u64 dAhi = make_desc(sbase + OF_AHI);
    const u64 dAlo = make_desc(sbase + OF_ALO);
    const u64 dB[2] = { make_desc(sbase + OF_B0), make_desc(sbase + OF_B1) };

    #pragma unroll 1
    for (int it = 0; it < 27; ++it) {
        if (it > 0) mbar_wait(sbase + OF_MBAR, (unsigned)((it - 1) & 1));
        if (it >= 1 && it + 1 < 27 && t == 0) {
            unsigned nb = (it + 1) & 1;
            unsigned tb = sbase + (nb ? OF_TBAR1 : OF_TBAR0);
            mbar_expect_tx(tb, 49152);
            bulk_g2s(sbase + (nb ? OF_B1 : OF_B0), bsrc + (size_t)(it + 1)*49152, 49152, tb);
        }
        const int ky = (it/3) / 3, kx = (it/3) % 3, cc = it % 3;
        #pragma unroll
        for (int u = t; u < 2048; u += 256) {
            int set = u >> 10, v = u & 1023, m = v >> 3, j = v & 7;
            int p = m & 63, bl = m >> 6;
            if (p >= 49) continue;
            float4 val = make_float4(0.f, 0.f, 0.f, 0.f);
            int oh = p/7 + ky - 1, ow = p%7 + kx - 1;
            if (oh >= 0 && oh < 7 && ow >= 0 && ow < 7)
                val = *(const float4*)(smem + OF_PL + (bl*2 + set)*PL_STRIDE
                                       + (oh*7 + ow)*400 + cc*128 + j*16);
            int off = m*128 + j*16;  off ^= (off >> 3) & 0x70;
            *(float4*)(smem + (set ? OF_ALO : OF_AHI) + off) = val;
        }
        asm volatile("fence.proxy.async.shared::cta;" ::: "memory");
        __syncthreads();

        if (wid == 0 && elect_one()) {
            const unsigned bsel = it & 1;
            mbar_wait(sbase + (bsel ? OF_TBAR1 : OF_TBAR0), (unsigned)((it >> 1) & 1));
            const u64 dBhi = dB[bsel];
            const u64 dBlo = dB[bsel] + (24576 >> 4);
            #pragma unroll
            for (int ks = 0; ks < 4; ++ks)
                mma_f16(tmem, dAhi + ks*2, dBhi + ks*2, MMA_IDESC, (it == 0 && ks == 0) ? 0u : 1u);
            #pragma unroll
            for (int ks = 0; ks < 4; ++ks)
                mma_f16(tmem, dAhi + ks*2, dBlo + ks*2, MMA_IDESC, 1u);
            #pragma unroll
            for (int ks = 0; ks < 4; ++ks)
                mma_f16(tmem, dAlo + ks*2, dBhi + ks*2, MMA_IDESC, 1u);
            tc_commit(sbase + OF_MBAR);
        }
    }
    mbar_wait(sbase + OF_MBAR, 0u);
    asm volatile("tcgen05.fence::after_thread_sync;" ::: "memory");

    // Epilogue: BN+GELU+residual, NHWC rows (contiguous 768B per position)
    if (wid < 4) {
        const int m = wid*32 + lane, p = m & 63, bl = m >> 6;
        const bool live = (p < 49);
        const float* sinv  = (const float*)(smem + OF_INV);
        const float* sbeta = (const float*)(smem + OF_BETA);
        float* drow = buf + (((size_t)(b0 + bl)*H + base_h + p/7)*H + base_w + p%7)*192;
        #pragma unroll 1
        for (int c0 = 0; c0 < 192; c0 += 32) {
            unsigned r[32];
            ldtm32(r, tmem + c0);
            tc_wait_ld();
            if (live) {
                #pragma unroll
                for (int q = 0; q < 8; ++q) {
                    float4 o;
                    float* ov = (float*)&o;
                    #pragma unroll
                    for (int e = 0; e < 4; ++e) {
                        int co = c0 + q*4 + e;
                        float a = __uint_as_float(r[q*4 + e]);
                        float y = gelu_exact(a*sinv[co] + sbeta[co]);
                        float rh = __bfloat162float(*(const __nv_bfloat16*)
                            (smem + OF_PL + (bl*2 + 0)*PL_STRIDE + p*400 + co*2));
                        float rl = __bfloat162float(*(const __nv_bfloat16*)
                            (smem + OF_PL + (bl*2 + 1)*PL_STRIDE + p*400 + co*2));
                        ov[e] = y + rh + rl;
                    }
                    *(float4*)(drow + c0 + q*4) = o;
                }
            }
        }
    }
    __syncthreads();
    if (wid == 0) tc_dealloc(tmem, 256);
#endif
}

// ---------------------------------------------------------------------------
// conv_mma: 2x2 stride-2 conv as tcgen05 bf16-split GEMM (NHWC in/out).
// CTA = (tile of 128 output positions, nh co-half). 12 iters = 4 k x 3 cc.
// ---------------------------------------------------------------------------
#define OC_TMEM   0
#define OC_MBAR   8
#define OC_TBAR0  16
#define OC_TBAR1  24
#define OC_INV    32
#define OC_BETA   (32 + 768)
#define OC_AHI    2048
#define OC_ALO    18432
#define OC_B0     34816
#define OC_B1     83968
#define CONV_SMEM 133120

template<bool GELU>
__global__ __launch_bounds__(256, 1)
void conv_mma(const __nv_bfloat16* __restrict__ blob,
              const float* __restrict__ src, float* __restrict__ dst,
              const float* __restrict__ bg, const float* __restrict__ bb,
              const float* __restrict__ bm, const float* __restrict__ bv,
              int SDIM, int ODIM, int dstStride)
{
#if TC_OK
    extern __shared__ char smem[];
    const int tile = blockIdx.x, nh = blockIdx.y;
    const int t = threadIdx.x, wid = t >> 5, lane = t & 31;
    const unsigned sbase = smem_u32(smem);
    const int SPOS = ODIM * ODIM;
    const char* bsrc = (const char*)blob + (size_t)nh * 12 * 49152;

    if (wid == 0) tc_alloc(sbase + OC_TMEM, 256);
    if (t < 192) {
        int gc = nh*192 + t;
        float inv = bg[gc] * rsqrtf(bv[gc] + EPS);
        ((float*)(smem + OC_INV))[t]  = inv;
        ((float*)(smem + OC_BETA))[t] = bb[gc] - bm[gc]*inv;
    }
    if (t == 0) {
        mbar_init(sbase + OC_MBAR, 1);
        mbar_init(sbase + OC_TBAR0, 1);
        mbar_init(sbase + OC_TBAR1, 1);
    }
    __syncthreads();
    if (t == 0) {
        mbar_expect_tx(sbase + OC_TBAR0, 49152);
        bulk_g2s(sbase + OC_B0, bsrc,          49152, sbase + OC_TBAR0);
        mbar_expect_tx(sbase + OC_TBAR1, 49152);
        bulk_g2s(sbase + OC_B1, bsrc + 49152,  49152, sbase + OC_TBAR1);
    }

    // per-thread A-gather constants: 2 tasks, rows m and m+64, 16-ci group qq
    const int m0 = t >> 2, qq = t & 3;
    size_t pixbase[2];
    unsigned sw0[2], sw1[2];
    #pragma unroll
    for (int s = 0; s < 2; ++s) {
        int m = m0 + s*64;
        int pos = tile*128 + m;
        int b = pos / SPOS, q = pos - b*SPOS;
        int oh = q / ODIM, ow = q - oh*ODIM;
        pixbase[s] = (((size_t)b*SDIM + 2*oh)*SDIM + 2*ow)*192 + qq*16;
        int boff = m*128 + qq*32;
        sw0[s] = boff ^ ((boff >> 3) & 0x70);
        sw1[s] = (boff + 16) ^ (((boff + 16) >> 3) & 0x70);
    }

    unsigned tmem;
    asm volatile("ld.shared.b32 %0, [%1];" : "=r"(tmem) : "r"(sbase + OC_TMEM));

    const u64 dAhi = make_desc(sbase + OC_AHI);
    const u64 dAlo = make_desc(sbase + OC_ALO);
    const u64 dB[2] = { make_desc(sbase + OC_B0), make_desc(sbase + OC_B1) };

    #pragma unroll 1
    for (int it = 0; it < 12; ++it) {
        if (it > 0) mbar_wait(sbase + OC_MBAR, (unsigned)((it - 1) & 1));
        if (it >= 1 && it + 1 < 12 && t == 0) {
            unsigned nb = (it + 1) & 1;
            unsigned tb = sbase + (nb ? OC_TBAR1 : OC_TBAR0);
            mbar_expect_tx(tb, 49152);
            bulk_g2s(sbase + (nb ? OC_B1 : OC_B0), bsrc + (size_t)(it + 1)*49152, 49152, tb);
        }
        const int k = it / 3, cc = it - 3*k;
        const int r = k >> 1, c = k & 1;
        const size_t koff = ((size_t)(r*SDIM + c))*192 + cc*64;

        #pragma unroll
        for (int s = 0; s < 2; ++s) {
            const float* gp = src + pixbase[s] + koff;
            float4 f[4];
            #pragma unroll
            for (int e = 0; e < 4; ++e) f[e] = *(const float4*)(gp + 4*e);
            unsigned hiw[8], low[8];
            const float* fv = (const float*)f;
            #pragma unroll
            for (int e = 0; e < 8; ++e) {
                __nv_bfloat16 ha, la, hb, lb;
                hl_split(fv[2*e],   ha, la);
                hl_split(fv[2*e+1], hb, lb);
                __nv_bfloat162 hp(ha, hb), lp(la, lb);
                hiw[e] = *(unsigned*)&hp;
                low[e] = *(unsigned*)&lp;
            }
            *(uint4*)(smem + OC_AHI + sw0[s]) = make_uint4(hiw[0], hiw[1], hiw[2], hiw[3]);
            *(uint4*)(smem + OC_AHI + sw1[s]) = make_uint4(hiw[4], hiw[5], hiw[6], hiw[7]);
            *(uint4*)(smem + OC_ALO + sw0[s]) = make_uint4(low[0], low[1], low[2], low[3]);
            *(uint4*)(smem + OC_ALO + sw1[s]) = make_uint4(low[4], low[5], low[6], low[7]);
        }
        asm volatile("fence.proxy.async.shared::cta;" ::: "memory");
        __syncthreads();

        if (wid == 0 && elect_one()) {
            const unsigned bsel = it & 1;
            mbar_wait(sbase + (bsel ? OC_TBAR1 : OC_TBAR0), (unsigned)((it >> 1) & 1));
            const u64 dBhi = dB[bsel];
            const u64 dBlo = dB[bsel] + (24576 >> 4);
            #pragma unroll
            for (int ks = 0; ks < 4; ++ks)
                mma_f16(tmem, dAhi + ks*2, dBhi + ks*2, MMA_IDESC, (it == 0 && ks == 0) ? 0u : 1u);
            #pragma unroll
            for (int ks = 0; ks < 4; ++ks)
                mma_f16(tmem, dAhi + ks*2, dBlo + ks*2, MMA_IDESC, 1u);
            #pragma unroll
            for (int ks = 0; ks < 4; ++ks)
                mma_f16(tmem, dAlo + ks*2, dBhi + ks*2, MMA_IDESC, 1u);
            tc_commit(sbase + OC_MBAR);
        }
    }
    mbar_wait(sbase + OC_MBAR, 1u);   // (12-1)&1
    asm volatile("tcgen05.fence::after_thread_sync;" ::: "memory");

    if (wid < 4) {
        const int m = wid*32 + lane;
        const int pos = tile*128 + m;
        const float* sinv  = (const float*)(smem + OC_INV);
        const float* sbeta = (const float*)(smem + OC_BETA);
        float* drow = dst + (size_t)pos*dstStride + nh*192;
        #pragma unroll 1
        for (int c0 = 0; c0 < 192; c0 += 32) {
            unsigned r[32];
            ldtm32(r, tmem + c0);
            tc_wait_ld();
            #pragma unroll
            for (int q = 0; q < 8; ++q) {
                float4 o;
                float* ov = (float*)&o;
                #pragma unroll
                for (int e = 0; e < 4; ++e) {
                    int co = c0 + q*4 + e;
                    float a = __uint_as_float(r[q*4 + e]);
                    float y = a*sinv[co] + sbeta[co];
                    ov[e] = GELU ? gelu_exact(y) : y;
                }
                *(float4*)(drow + c0 + q*4) = o;
            }
        }
    }
    __syncthreads();
    if (wid == 0) tc_dealloc(tmem, 256);
#endif
}

// ---------------------------------------------------------------------------
extern "C" void kernel_launch(void* const* d_in, const int* in_sizes, int n_in,
                              void* d_out, int out_size)
{
    const float* x       = (const float*)d_in[0];
    const float* c1w     = (const float*)d_in[1];
    const float* b1g = (const float*)d_in[2],  *b1b = (const float*)d_in[3];
    const float* b1m = (const float*)d_in[4],  *b1v = (const float*)d_in[5];
    const float* r1w     = (const float*)d_in[6];
    const float* r1g = (const float*)d_in[7],  *r1b = (const float*)d_in[8];
    const float* r1m = (const float*)d_in[9],  *r1v = (const float*)d_in[10];
    const float* c2w     = (const float*)d_in[11];
    const float* b2g = (const float*)d_in[12], *b2b = (const float*)d_in[13];
    const float* b2m = (const float*)d_in[14], *b2v = (const float*)d_in[15];
    const float* r2w     = (const float*)d_in[16];
    const float* r2g = (const float*)d_in[17], *r2b = (const float*)d_in[18];
    const float* r2m = (const float*)d_in[19], *r2v = (const float*)d_in[20];
    const float* c3w     = (const float*)d_in[21];
    const float* b3g = (const float*)d_in[22], *b3b = (const float*)d_in[23];
    const float* b3m = (const float*)d_in[24], *b3v = (const float*)d_in[25];
    float* out = (float*)d_out;

    __nv_bfloat16 *blob1, *blob2, *blob2c, *blob3c;
    float *bufA, *bufB;
    cudaGetSymbolAddress((void**)&blob1, g_blob1);
    cudaGetSymbolAddress((void**)&blob2, g_blob2);
    cudaGetSymbolAddress((void**)&blob2c, g_blob2c);
    cudaGetSymbolAddress((void**)&blob3c, g_blob3c);
    cudaGetSymbolAddress((void**)&bufA, g_bufA);
    cudaGetSymbolAddress((void**)&bufB, g_bufB);

    {   // weight prep
        int t1 = 64*9*3*192*64;
        prep_region_blob<<<(t1 + 255)/256, 256>>>(r1w, blob1, t1);
        int t2 = 16*9*3*192*64;
        prep_region_blob<<<(t2 + 255)/256, 256>>>(r2w, blob2, t2);
        int t3 = 64*192*12;
        prep_conv_blob<<<(t3 + 255)/256, 256>>>(c2w, blob2c, 192, t3);
        int t4 = 64*768*12;
        prep_conv_blob<<<(t4 + 255)/256, 256>>>(c3w, blob3c, 768, t4);
    }

    cudaFuncSetAttribute(region_mma, cudaFuncAttributeMaxDynamicSharedMemorySize, REGION_SMEM);
    cudaFuncSetAttribute(conv_mma<true>,  cudaFuncAttributeMaxDynamicSharedMemorySize, CONV_SMEM);
    cudaFuncSetAttribute(conv_mma<false>, cudaFuncAttributeMaxDynamicSharedMemorySize, CONV_SMEM);

    conv1_kernel<<<dim3(56, 64), 192>>>(x, c1w, b1g, b1b, b1m, b1v);
    region_mma<<<dim3(32, 64), 256, REGION_SMEM>>>(blob1, r1g, r1b, r1m, r1v, 56);
    conv_mma<true><<<dim3(392, 1), 256, CONV_SMEM>>>(blob2c, bufA, bufB,
                                                     b2g, b2b, b2m, b2v, 56, 28, 192);
    region_mma<<<dim3(32, 16), 256, REGION_SMEM>>>(blob2, r2g, r2b, r2m, r2v, 28);
    conv_mma<false><<<dim3(98, 4), 256, CONV_SMEM>>>(blob3c, bufB, out,
                                                     b3g, b3b, b3m, b3v, 28, 14, 768);
}